// round 5
// baseline (speedup 1.0000x reference)
#include <cuda_runtime.h>
#include <math.h>
#include <stdint.h>

#define NNODE 8192
#define DDIM  256
#define NPG   256
#define BGRP  32
#define NEDGE 131072
#define NMASK (BGRP * NPG)
#define ZERO_EPS 1e-8f

// ---------------- scratch ----------------------------------------------------
__device__ float g_H0[NNODE * DDIM];
__device__ float g_H1[NNODE * DDIM];
__device__ float g_G[3 * NNODE * DDIM];
__device__ float g_HT[NNODE * DDIM];
__device__ float g_Ablk[BGRP * NPG * NPG];
__device__ float g_Adj[3 * BGRP * NPG * NPG];
__device__ float g_nrm[NNODE];
__device__ float g_rinv[NNODE];
__device__ float g_sc[NNODE];
__device__ float g_svec[DDIM];
__device__ float g_emf[NMASK];
__device__ float g_pmf[NMASK];
__device__ int   g_mask_mode;

// ---------------- tf32 helpers ----------------------------------------------
__device__ __forceinline__ float tf32_rna(float x) {
    uint32_t u;
    asm("cvt.rna.tf32.f32 %0, %1;" : "=r"(u) : "f"(x));
    return __uint_as_float(u);
}

__device__ __forceinline__ void mma8(float c[4], const float a[4], float b0, float b1) {
    asm volatile("mma.sync.aligned.m16n8k8.row.col.f32.tf32.tf32.f32 "
        "{%0,%1,%2,%3}, {%4,%5,%6,%7}, {%8,%9}, {%0,%1,%2,%3};"
        : "+f"(c[0]), "+f"(c[1]), "+f"(c[2]), "+f"(c[3])
        : "r"(__float_as_uint(a[0])), "r"(__float_as_uint(a[1])),
          "r"(__float_as_uint(a[2])), "r"(__float_as_uint(a[3])),
          "r"(__float_as_uint(b0)),  "r"(__float_as_uint(b1)));
}

// ---------------- 128x128xK(=256) 3xTF32 mainloop ----------------------------
// Block = 256 thr = 8 warps in 4(M)x2(N); warp tile 32x64; mma m16n8k8.
// A row-major MxK (Ag at tile row 0), lda.
// NT=false: B row-major KxN (Bg at tile col 0), ldb.
// NT=true : B row-major NxK (Bg at tile row 0), ldb -> computes A @ B^T.
// smem partitions (floats):
//   sAH [2][128][20], sAL [2][128][20]
//   NN: sBH/[2][16][136], sBL same;  NT: sBH/[2][128][20], sBL same.
#define AIDX(b,r,k) ((b)*2560 + (r)*20 + (k))
#define BNNI(b,k,n) ((b)*2176 + (k)*136 + (n))
#define BNTI(b,n,k) ((b)*2560 + (n)*20 + (k))

template<bool NT>
__device__ __forceinline__ void mma_loop(const float* __restrict__ Ag, int lda,
                                         const float* __restrict__ Bg, int ldb,
                                         float* __restrict__ smem,
                                         float (*acc)[8][4])
{
    const int tid  = threadIdx.x;
    const int lane = tid & 31;
    const int warp = tid >> 5;
    const int gid  = lane >> 2, tig = lane & 3;
    const int wm   = (warp & 3) * 32, wn = (warp >> 2) * 64;
    const int ar   = tid >> 2, ac4 = (tid & 3) << 2;   // A / NT-B loader
    const int bk   = tid >> 5, bn4 = (tid & 31) << 2;  // NN-B loader

    float* sAH = smem;
    float* sAL = smem + 5120;
    float* sBH = smem + 10240;
    float* sBL = sBH + (NT ? 5120 : 4352);

    float4 pa0, pa1, pb0, pb1;

    // ---- stage-0 load + store ----
    pa0 = *(const float4*)(Ag + (size_t)ar * lda + ac4);
    pa1 = *(const float4*)(Ag + (size_t)(ar + 64) * lda + ac4);
    if (NT) {
        pb0 = *(const float4*)(Bg + (size_t)ar * ldb + ac4);
        pb1 = *(const float4*)(Bg + (size_t)(ar + 64) * ldb + ac4);
    } else {
        pb0 = *(const float4*)(Bg + (size_t)bk * ldb + bn4);
        pb1 = *(const float4*)(Bg + (size_t)(bk + 8) * ldb + bn4);
    }
    {
        const int buf = 0;
        float va[8] = {pa0.x, pa0.y, pa0.z, pa0.w, pa1.x, pa1.y, pa1.z, pa1.w};
        #pragma unroll
        for (int i = 0; i < 8; i++) {
            int r = (i < 4) ? ar : ar + 64;
            int k = ac4 + (i & 3);
            float hi = tf32_rna(va[i]);
            sAH[AIDX(buf, r, k)] = hi;
            sAL[AIDX(buf, r, k)] = tf32_rna(va[i] - hi);
        }
        float vb[8] = {pb0.x, pb0.y, pb0.z, pb0.w, pb1.x, pb1.y, pb1.z, pb1.w};
        #pragma unroll
        for (int i = 0; i < 8; i++) {
            float hi = tf32_rna(vb[i]);
            float lo = tf32_rna(vb[i] - hi);
            if (NT) {
                int r = (i < 4) ? ar : ar + 64;
                int k = ac4 + (i & 3);
                sBH[BNTI(buf, r, k)] = hi; sBL[BNTI(buf, r, k)] = lo;
            } else {
                int k = (i < 4) ? bk : bk + 8;
                int n = bn4 + (i & 3);
                sBH[BNNI(buf, k, n)] = hi; sBL[BNNI(buf, k, n)] = lo;
            }
        }
    }
    __syncthreads();

    for (int s = 0; s < 16; s++) {
        const int buf = s & 1;
        if (s < 15) {
            const int s1 = (s + 1) * 16;
            pa0 = *(const float4*)(Ag + (size_t)ar * lda + s1 + ac4);
            pa1 = *(const float4*)(Ag + (size_t)(ar + 64) * lda + s1 + ac4);
            if (NT) {
                pb0 = *(const float4*)(Bg + (size_t)ar * ldb + s1 + ac4);
                pb1 = *(const float4*)(Bg + (size_t)(ar + 64) * ldb + s1 + ac4);
            } else {
                pb0 = *(const float4*)(Bg + (size_t)(s1 + bk) * ldb + bn4);
                pb1 = *(const float4*)(Bg + (size_t)(s1 + bk + 8) * ldb + bn4);
            }
        }
        // ---- compute on buf ----
        #pragma unroll
        for (int kg = 0; kg < 2; kg++) {
            const int k0 = kg * 8 + tig;
            float ah[2][4], al[2][4];
            #pragma unroll
            for (int mt = 0; mt < 2; mt++) {
                const int r0 = wm + mt * 16 + gid;
                ah[mt][0] = sAH[AIDX(buf, r0,     k0)];
                ah[mt][1] = sAH[AIDX(buf, r0 + 8, k0)];
                ah[mt][2] = sAH[AIDX(buf, r0,     k0 + 4)];
                ah[mt][3] = sAH[AIDX(buf, r0 + 8, k0 + 4)];
                al[mt][0] = sAL[AIDX(buf, r0,     k0)];
                al[mt][1] = sAL[AIDX(buf, r0 + 8, k0)];
                al[mt][2] = sAL[AIDX(buf, r0,     k0 + 4)];
                al[mt][3] = sAL[AIDX(buf, r0 + 8, k0 + 4)];
            }
            #pragma unroll
            for (int nt = 0; nt < 8; nt++) {
                const int cn = wn + nt * 8 + gid;
                float bh0, bh1, bl0, bl1;
                if (NT) {
                    bh0 = sBH[BNTI(buf, cn, k0)];
                    bh1 = sBH[BNTI(buf, cn, k0 + 4)];
                    bl0 = sBL[BNTI(buf, cn, k0)];
                    bl1 = sBL[BNTI(buf, cn, k0 + 4)];
                } else {
                    bh0 = sBH[BNNI(buf, k0,     cn)];
                    bh1 = sBH[BNNI(buf, k0 + 4, cn)];
                    bl0 = sBL[BNNI(buf, k0,     cn)];
                    bl1 = sBL[BNNI(buf, k0 + 4, cn)];
                }
                #pragma unroll
                for (int mt = 0; mt < 2; mt++) {
                    mma8(acc[mt][nt], ah[mt], bh0, bh1);
                    mma8(acc[mt][nt], al[mt], bh0, bh1);
                    mma8(acc[mt][nt], ah[mt], bl0, bl1);
                }
            }
        }
        // ---- store prefetched into other buffer ----
        if (s < 15) {
            const int nb = buf ^ 1;
            float va[8] = {pa0.x, pa0.y, pa0.z, pa0.w, pa1.x, pa1.y, pa1.z, pa1.w};
            #pragma unroll
            for (int i = 0; i < 8; i++) {
                int r = (i < 4) ? ar : ar + 64;
                int k = ac4 + (i & 3);
                float hi = tf32_rna(va[i]);
                sAH[AIDX(nb, r, k)] = hi;
                sAL[AIDX(nb, r, k)] = tf32_rna(va[i] - hi);
            }
            float vb[8] = {pb0.x, pb0.y, pb0.z, pb0.w, pb1.x, pb1.y, pb1.z, pb1.w};
            #pragma unroll
            for (int i = 0; i < 8; i++) {
                float hi = tf32_rna(vb[i]);
                float lo = tf32_rna(vb[i] - hi);
                if (NT) {
                    int r = (i < 4) ? ar : ar + 64;
                    int k = ac4 + (i & 3);
                    sBH[BNTI(nb, r, k)] = hi; sBL[BNTI(nb, r, k)] = lo;
                } else {
                    int k = (i < 4) ? bk : bk + 8;
                    int n = bn4 + (i & 3);
                    sBH[BNNI(nb, k, n)] = hi; sBL[BNNI(nb, k, n)] = lo;
                }
            }
        }
        __syncthreads();
    }
}

#define SMEM_NN 75776
#define SMEM_NT 81920

// ---------------- GEMM kernels ----------------------------------------------
// C[z] = A(NNODE x D) @ W[z](D x D)
__global__ __launch_bounds__(256, 2) void k_gemm_nn(const float* __restrict__ A,
                                                    const float* __restrict__ W,
                                                    float* __restrict__ C) {
    extern __shared__ float smem[];
    const int m0 = blockIdx.y * 128, n0 = blockIdx.x * 128, z = blockIdx.z;
    float acc[2][8][4];
    #pragma unroll
    for (int i = 0; i < 2; i++)
        #pragma unroll
        for (int j = 0; j < 8; j++)
            #pragma unroll
            for (int q = 0; q < 4; q++) acc[i][j][q] = 0.f;
    mma_loop<false>(A + (size_t)m0 * DDIM, DDIM,
                    W + (size_t)z * DDIM * DDIM + n0, DDIM, smem, acc);
    float* Cg = C + (size_t)z * NNODE * DDIM;
    const int lane = threadIdx.x & 31, warp = threadIdx.x >> 5;
    const int gid = lane >> 2, tig = lane & 3;
    const int wm = (warp & 3) * 32, wn = (warp >> 2) * 64;
    #pragma unroll
    for (int mt = 0; mt < 2; mt++)
        #pragma unroll
        for (int nt = 0; nt < 8; nt++) {
            int r = m0 + wm + mt * 16 + gid;
            int c = n0 + wn + nt * 8 + 2 * tig;
            *(float2*)&Cg[(size_t)r * DDIM + c] = make_float2(acc[mt][nt][0], acc[mt][nt][1]);
            *(float2*)&Cg[(size_t)(r + 8) * DDIM + c] = make_float2(acc[mt][nt][2], acc[mt][nt][3]);
        }
}

// Ablk[b] = (X_b X_b^T) * sc_i * sc_j
__global__ __launch_bounds__(256, 2) void k_corr(const float* __restrict__ x,
                                                 const float* __restrict__ sc,
                                                 float* __restrict__ Ablk) {
    extern __shared__ float smem[];
    const int m0 = blockIdx.y * 128, n0 = blockIdx.x * 128, b = blockIdx.z;
    const float* base = x + (size_t)b * NPG * DDIM;
    float acc[2][8][4];
    #pragma unroll
    for (int i = 0; i < 2; i++)
        #pragma unroll
        for (int j = 0; j < 8; j++)
            #pragma unroll
            for (int q = 0; q < 4; q++) acc[i][j][q] = 0.f;
    mma_loop<true>(base + (size_t)m0 * DDIM, DDIM,
                   base + (size_t)n0 * DDIM, DDIM, smem, acc);
    const int lane = threadIdx.x & 31, warp = threadIdx.x >> 5;
    const int gid = lane >> 2, tig = lane & 3;
    const int wm = (warp & 3) * 32, wn = (warp >> 2) * 64;
    const float* scb = sc + b * NPG;
    #pragma unroll
    for (int mt = 0; mt < 2; mt++)
        #pragma unroll
        for (int nt = 0; nt < 8; nt++) {
            int li = m0 + wm + mt * 16 + gid;
            int lj = n0 + wn + nt * 8 + 2 * tig;
            float s0 = scb[li], s1 = scb[li + 8];
            float c0 = scb[lj], c1 = scb[lj + 1];
            float* row0 = Ablk + ((size_t)b * NPG + li) * NPG;
            float* row1 = Ablk + ((size_t)b * NPG + li + 8) * NPG;
            *(float2*)&row0[lj] = make_float2(acc[mt][nt][0] * s0 * c0, acc[mt][nt][1] * s0 * c1);
            *(float2*)&row1[lj] = make_float2(acc[mt][nt][2] * s1 * c0, acc[mt][nt][3] * s1 * c1);
        }
}

// Hout[b] = relu( sum_t Adj_t[b] @ G_t[b] + sum_t bias_t )
__global__ __launch_bounds__(256, 2) void k_aggr(const float* __restrict__ Adj,
                                                 const float* __restrict__ G,
                                                 const float* __restrict__ bg,
                                                 float* __restrict__ Hout) {
    extern __shared__ float smem[];
    const int m0 = blockIdx.y * 128, n0 = blockIdx.x * 128, b = blockIdx.z;
    float acc[2][8][4];
    #pragma unroll
    for (int i = 0; i < 2; i++)
        #pragma unroll
        for (int j = 0; j < 8; j++)
            #pragma unroll
            for (int q = 0; q < 4; q++) acc[i][j][q] = 0.f;
    for (int t = 0; t < 3; t++) {
        const float* Ag = Adj + ((size_t)(t * BGRP + b)) * NPG * NPG + (size_t)m0 * NPG;
        const float* Bg = G + (size_t)t * NNODE * DDIM + (size_t)b * NPG * DDIM + n0;
        mma_loop<false>(Ag, NPG, Bg, DDIM, smem, acc);
    }
    const int lane = threadIdx.x & 31, warp = threadIdx.x >> 5;
    const int gid = lane >> 2, tig = lane & 3;
    const int wm = (warp & 3) * 32, wn = (warp >> 2) * 64;
    #pragma unroll
    for (int mt = 0; mt < 2; mt++)
        #pragma unroll
        for (int nt = 0; nt < 8; nt++) {
            int li = m0 + wm + mt * 16 + gid;
            int c = n0 + wn + nt * 8 + 2 * tig;
            float bsum0 = bg[c] + bg[DDIM + c] + bg[2 * DDIM + c];
            float bsum1 = bg[c + 1] + bg[DDIM + c + 1] + bg[2 * DDIM + c + 1];
            float* row0 = Hout + ((size_t)b * NPG + li) * DDIM;
            float* row1 = Hout + ((size_t)b * NPG + li + 8) * DDIM;
            *(float2*)&row0[c] = make_float2(fmaxf(acc[mt][nt][0] + bsum0, 0.f),
                                             fmaxf(acc[mt][nt][1] + bsum1, 0.f));
            *(float2*)&row1[c] = make_float2(fmaxf(acc[mt][nt][2] + bsum0, 0.f),
                                             fmaxf(acc[mt][nt][3] + bsum1, 0.f));
        }
}

// Ablk[b] = 0.5*Ablk[b] + 0.5*sigmoid( HT_b @ Hn_b^T )
__global__ __launch_bounds__(256, 2) void k_ahat(const float* __restrict__ HT,
                                                 const float* __restrict__ Hn,
                                                 float* __restrict__ Ablk) {
    extern __shared__ float smem[];
    const int m0 = blockIdx.y * 128, n0 = blockIdx.x * 128, b = blockIdx.z;
    float acc[2][8][4];
    #pragma unroll
    for (int i = 0; i < 2; i++)
        #pragma unroll
        for (int j = 0; j < 8; j++)
            #pragma unroll
            for (int q = 0; q < 4; q++) acc[i][j][q] = 0.f;
    mma_loop<true>(HT + ((size_t)b * NPG + m0) * DDIM, DDIM,
                   Hn + ((size_t)b * NPG + n0) * DDIM, DDIM, smem, acc);
    const int lane = threadIdx.x & 31, warp = threadIdx.x >> 5;
    const int gid = lane >> 2, tig = lane & 3;
    const int wm = (warp & 3) * 32, wn = (warp >> 2) * 64;
    #pragma unroll
    for (int mt = 0; mt < 2; mt++)
        #pragma unroll
        for (int nt = 0; nt < 8; nt++) {
            int li = m0 + wm + mt * 16 + gid;
            int lj = n0 + wn + nt * 8 + 2 * tig;
            float* row0 = Ablk + ((size_t)b * NPG + li) * NPG;
            float* row1 = Ablk + ((size_t)b * NPG + li + 8) * NPG;
            float2 o0 = *(const float2*)&row0[lj];
            float2 o1 = *(const float2*)&row1[lj];
            float2 v0, v1;
            v0.x = 0.5f * o0.x + 0.5f / (1.0f + expf(-acc[mt][nt][0]));
            v0.y = 0.5f * o0.y + 0.5f / (1.0f + expf(-acc[mt][nt][1]));
            v1.x = 0.5f * o1.x + 0.5f / (1.0f + expf(-acc[mt][nt][2]));
            v1.y = 0.5f * o1.y + 0.5f / (1.0f + expf(-acc[mt][nt][3]));
            *(float2*)&row0[lj] = v0;
            *(float2*)&row1[lj] = v1;
        }
}

// ---------------- small kernels ---------------------------------------------
__global__ void k_mask_detect(const unsigned char* __restrict__ em,
                              const unsigned char* __restrict__ pm) {
    __shared__ int nz[4];
    if (threadIdx.x < 4) nz[threadIdx.x] = 0;
    __syncthreads();
    int loc[4] = {0, 0, 0, 0};
    for (int i = threadIdx.x; i < NMASK; i += 256) {
        if (em[i]) loc[i & 3]++;
        if (pm[i]) loc[i & 3]++;
    }
    #pragma unroll
    for (int j = 0; j < 4; j++) if (loc[j]) atomicAdd(&nz[j], loc[j]);
    __syncthreads();
    if (threadIdx.x == 0) {
        int mode;
        if (nz[1] > 0) mode = 0;
        else if (nz[0] > 0) mode = 1;
        else mode = 2;
        g_mask_mode = mode;
    }
}

__global__ void k_mask_decode(const unsigned char* __restrict__ em,
                              const unsigned char* __restrict__ pm,
                              float* __restrict__ emf, float* __restrict__ pmf) {
    int i = blockIdx.x * blockDim.x + threadIdx.x;
    if (i >= NMASK) return;
    int mode = g_mask_mode;
    float e, p;
    if (mode == 0) {
        e = em[i] ? 1.f : 0.f;
        p = pm[i] ? 1.f : 0.f;
    } else if (mode == 1) {
        e = ((const int*)em)[i] ? 1.f : 0.f;
        p = ((const int*)pm)[i] ? 1.f : 0.f;
    } else {
        e = (((const float*)em)[i] != 0.f) ? 1.f : 0.f;
        p = (((const float*)pm)[i] != 0.f) ? 1.f : 0.f;
    }
    emf[i] = e; pmf[i] = p;
}

__global__ void k_rownorm(const float* __restrict__ x, float* __restrict__ nrm,
                          float* __restrict__ rinv) {
    int warp = (blockIdx.x * blockDim.x + threadIdx.x) >> 5;
    int lane = threadIdx.x & 31;
    if (warp >= NNODE) return;
    const float* r = x + (size_t)warp * DDIM;
    float s = 0.f;
    for (int j = lane; j < DDIM; j += 32) { float v = r[j]; s += v * v; }
    #pragma unroll
    for (int o = 16; o; o >>= 1) s += __shfl_xor_sync(0xffffffffu, s, o);
    if (!lane) { float n = sqrtf(s); nrm[warp] = n; rinv[warp] = 1.0f / n; }
}

__global__ void k_colsum(const float* __restrict__ x, const float* __restrict__ rinv,
                         float* __restrict__ svec) {
    int d = threadIdx.x;
    int r0 = blockIdx.x * 32;   // 256 blocks * 32 rows
    float acc = 0.f;
    for (int r = r0; r < r0 + 32; r++)
        acc += x[(size_t)r * DDIM + d] * rinv[r];
    atomicAdd(&svec[d], acc);
}

__global__ void k_scale(const float* __restrict__ x, const float* __restrict__ rinv,
                        const float* __restrict__ svec, float* __restrict__ sc) {
    int warp = (blockIdx.x * blockDim.x + threadIdx.x) >> 5;
    int lane = threadIdx.x & 31;
    if (warp >= NNODE) return;
    const float* r = x + (size_t)warp * DDIM;
    float dot = 0.f;
    for (int j = lane; j < DDIM; j += 32) dot += r[j] * svec[j];
    #pragma unroll
    for (int o = 16; o; o >>= 1) dot += __shfl_xor_sync(0xffffffffu, dot, o);
    if (!lane) {
        float rowsum = dot * rinv[warp];
        sc[warp] = rsqrtf(fabsf(rowsum) + ZERO_EPS) * rinv[warp];
    }
}

__global__ void k_scatter_w(const int* __restrict__ ei, const float* __restrict__ ew,
                            float* __restrict__ Adj) {
    int e = blockIdx.x * blockDim.x + threadIdx.x;
    if (e >= NEDGE) return;
    int src = ei[e], dst = ei[NEDGE + e];
    int b = src >> 8, sl = src & 255, dl = dst & 255;
    atomicAdd(&Adj[(((size_t)b << 8) + dl) * NPG + sl], ew[e]);
}

__global__ void k_scatter_A(const int* __restrict__ ei, const float* __restrict__ Ablk,
                            float* __restrict__ Adj) {
    int e = blockIdx.x * blockDim.x + threadIdx.x;
    if (e >= NEDGE) return;
    int src = ei[e], dst = ei[NEDGE + e];
    int b = src >> 8, sl = src & 255, dl = dst & 255;
    float w = Ablk[(((size_t)b << 8) + sl) * NPG + dl];
    atomicAdd(&Adj[(((size_t)b << 8) + dl) * NPG + sl], w);
}

// ---------------- final maps ------------------------------------------------
__global__ __launch_bounds__(256) void k_final(const float* __restrict__ Ablk,
                                               const float* __restrict__ emf,
                                               const float* __restrict__ pmf,
                                               float* __restrict__ out) {
    int b = blockIdx.x;
    __shared__ float ems[NPG], pms[NPG];
    __shared__ float me[NPG], mp[NPG];
    __shared__ float red[256];
    int t = threadIdx.x;
    ems[t] = emf[b * NPG + t];
    pms[t] = pmf[b * NPG + t];
    __syncthreads();
    int warp = t >> 5, lane = t & 31;
    for (int r = warp; r < NPG; r += 8) {
        const float* row = Ablk + ((size_t)b * NPG + r) * NPG;
        float s = 0.f, es = 0.f, ps = 0.f;
        for (int j = lane; j < NPG; j += 32) {
            float a = row[j];
            s += a; es += a * ems[j]; ps += a * pms[j];
        }
        #pragma unroll
        for (int o = 16; o; o >>= 1) {
            s  += __shfl_xor_sync(0xffffffffu, s, o);
            es += __shfl_xor_sync(0xffffffffu, es, o);
            ps += __shfl_xor_sync(0xffffffffu, ps, o);
        }
        if (!lane) { me[r] = s - ps; mp[r] = s - es; }
    }
    __syncthreads();
    for (int pass = 0; pass < 2; pass++) {
        float v = pass ? mp[t] : me[t];
        red[t] = v; __syncthreads();
        for (int s2 = 128; s2; s2 >>= 1) {
            if (t < s2) red[t] = fminf(red[t], red[t + s2]);
            __syncthreads();
        }
        float mn = red[0]; __syncthreads();
        red[t] = v; __syncthreads();
        for (int s2 = 128; s2; s2 >>= 1) {
            if (t < s2) red[t] = fmaxf(red[t], red[t + s2]);
            __syncthreads();
        }
        float mx = red[0]; __syncthreads();
        float u = (v - mn) / (mx - mn + ZERO_EPS);
        red[t] = u; __syncthreads();
        for (int s2 = 128; s2; s2 >>= 1) {
            if (t < s2) red[t] += red[t + s2];
            __syncthreads();
        }
        float sm = red[0]; __syncthreads();
        out[pass * (BGRP * NPG) + b * NPG + t] = u / (sm + ZERO_EPS);
    }
}

// ---------------- host ------------------------------------------------------
extern "C" void kernel_launch(void* const* d_in, const int* in_sizes, int n_in,
                              void* d_out, int out_size) {
    const float*     x    = (const float*)d_in[0];
    const int*       ei_e = (const int*)d_in[1];
    const float*     ew_e = (const float*)d_in[2];
    const int*       ei_p = (const int*)d_in[3];
    const float*     ew_p = (const float*)d_in[4];
    const int*       ei_o = (const int*)d_in[5];
    const float*     ew_o = (const float*)d_in[6];
    const unsigned char* em = (const unsigned char*)d_in[7];
    const unsigned char* pm = (const unsigned char*)d_in[8];
    const float*     Wg   = (const float*)d_in[9];
    const float*     bg   = (const float*)d_in[10];
    const float*     Td   = (const float*)d_in[11];
    float* out = (float*)d_out;

    float *H0, *H1, *G, *HT, *Ablk, *Adj, *nrm, *rinv, *sc, *svec, *emf, *pmf;
    cudaGetSymbolAddress((void**)&H0,   g_H0);
    cudaGetSymbolAddress((void**)&H1,   g_H1);
    cudaGetSymbolAddress((void**)&G,    g_G);
    cudaGetSymbolAddress((void**)&HT,   g_HT);
    cudaGetSymbolAddress((void**)&Ablk, g_Ablk);
    cudaGetSymbolAddress((void**)&Adj,  g_Adj);
    cudaGetSymbolAddress((void**)&nrm,  g_nrm);
    cudaGetSymbolAddress((void**)&rinv, g_rinv);
    cudaGetSymbolAddress((void**)&sc,   g_sc);
    cudaGetSymbolAddress((void**)&svec, g_svec);
    cudaGetSymbolAddress((void**)&emf,  g_emf);
    cudaGetSymbolAddress((void**)&pmf,  g_pmf);

    static int attr_done = 0;
    if (!attr_done) {
        cudaFuncSetAttribute(k_gemm_nn, cudaFuncAttributeMaxDynamicSharedMemorySize, SMEM_NT);
        cudaFuncSetAttribute(k_aggr,    cudaFuncAttributeMaxDynamicSharedMemorySize, SMEM_NT);
        cudaFuncSetAttribute(k_corr,    cudaFuncAttributeMaxDynamicSharedMemorySize, SMEM_NT);
        cudaFuncSetAttribute(k_ahat,    cudaFuncAttributeMaxDynamicSharedMemorySize, SMEM_NT);
        attr_done = 1;
    }

    const size_t ADJ1 = (size_t)BGRP * NPG * NPG;

    // masks
    k_mask_detect<<<1, 256>>>(em, pm);
    k_mask_decode<<<NMASK / 256, 256>>>(em, pm, emf, pmf);

    // prologue
    cudaMemsetAsync(Adj, 0, 3 * ADJ1 * sizeof(float));
    cudaMemsetAsync(svec, 0, DDIM * sizeof(float));
    k_rownorm<<<NNODE / 8, 256>>>(x, nrm, rinv);
    k_colsum<<<256, 256>>>(x, rinv, svec);
    k_scale<<<NNODE / 8, 256>>>(x, rinv, svec, sc);
    k_corr<<<dim3(2, 2, BGRP), 256, SMEM_NT>>>(x, sc, Ablk);

    // layer-0 adjacency
    k_scatter_w<<<NEDGE / 256, 256>>>(ei_e, ew_e, Adj);
    k_scatter_w<<<NEDGE / 256, 256>>>(ei_p, ew_p, Adj + ADJ1);
    k_scatter_w<<<NEDGE / 256, 256>>>(ei_o, ew_o, Adj + 2 * ADJ1);

    // layer 0
    k_gemm_nn<<<dim3(2, 64, 3), 256, SMEM_NN>>>(x, Wg, G);
    k_aggr<<<dim3(2, 2, BGRP), 256, SMEM_NN>>>(Adj, G, bg, H0);
    k_gemm_nn<<<dim3(2, 64, 1), 256, SMEM_NN>>>(H0, Td, HT);
    k_ahat<<<dim3(2, 2, BGRP), 256, SMEM_NT>>>(HT, H0, Ablk);

    // layer-1 adjacency
    cudaMemsetAsync(Adj, 0, 3 * ADJ1 * sizeof(float));
    k_scatter_A<<<NEDGE / 256, 256>>>(ei_e, Ablk, Adj);
    k_scatter_A<<<NEDGE / 256, 256>>>(ei_p, Ablk, Adj + ADJ1);
    k_scatter_A<<<NEDGE / 256, 256>>>(ei_o, Ablk, Adj + 2 * ADJ1);

    // layer 1
    k_gemm_nn<<<dim3(2, 64, 3), 256, SMEM_NN>>>(H0, Wg + 3 * DDIM * DDIM, G);
    k_aggr<<<dim3(2, 2, BGRP), 256, SMEM_NN>>>(Adj, G, bg + 3 * DDIM, H1);
    k_gemm_nn<<<dim3(2, 64, 1), 256, SMEM_NN>>>(H1, Td + DDIM * DDIM, HT);
    k_ahat<<<dim3(2, 2, BGRP), 256, SMEM_NT>>>(HT, H1, Ablk);

    // final maps
    k_final<<<BGRP, 256>>>(Ablk, emf, pmf, out);
}

// round 6
// speedup vs baseline: 1.1595x; 1.1595x over previous
#include <cuda_runtime.h>
#include <math.h>
#include <stdint.h>

#define NNODE 8192
#define DDIM  256
#define NPG   256
#define BGRP  32
#define NEDGE 131072
#define NMASK (BGRP * NPG)
#define ZERO_EPS 1e-8f

typedef unsigned long long u64;

// ---------------- scratch ----------------------------------------------------
__device__ float g_H0[NNODE * DDIM];
__device__ float g_H1[NNODE * DDIM];
__device__ float g_G[3 * NNODE * DDIM];
__device__ float g_HT[NNODE * DDIM];
__device__ float g_Ablk[BGRP * NPG * NPG];
__device__ float g_Adj[3 * BGRP * NPG * NPG];
__device__ float g_nrm[NNODE];
__device__ float g_rinv[NNODE];
__device__ float g_sc[NNODE];
__device__ float g_svec[DDIM];
__device__ float g_emf[NMASK];
__device__ float g_pmf[NMASK];
__device__ int   g_mask_mode;

// ---------------- f32x2 packed helpers ---------------------------------------
__device__ __forceinline__ u64 ffma2(u64 a, u64 b, u64 c) {
    asm("fma.rn.f32x2 %0, %1, %2, %3;" : "=l"(c) : "l"(a), "l"(b), "l"(c));
    return c;
}
__device__ __forceinline__ u64 pack2(float v) {
    u64 u = __float_as_uint(v);
    return (u << 32) | u;
}
__device__ __forceinline__ float plo(u64 x) { return __uint_as_float((unsigned)x); }
__device__ __forceinline__ float phi(u64 x) { return __uint_as_float((unsigned)(x >> 32)); }

// ---------------- 128x128x8 double-buffered FFMA2 mainloop -------------------
// A row-major MxK (Ag at tile row 0), lda. A staged duplicated: sAd[k][m]={v,v}.
// NT=false: B row-major KxN (Bg at tile col 0), ldb.
// NT=true : B row-major NxK (Bg at tile row 0), ldb -> computes A @ B^T.
// sAd: u64 [2][8][128] (16KB), sB: float [2][8][128] (8KB).
template<bool NT>
__device__ __forceinline__ void mm128x2(const float* __restrict__ Ag, int lda,
                                        const float* __restrict__ Bg, int ldb,
                                        int K,
                                        u64* __restrict__ sAd,
                                        float* __restrict__ sB,
                                        u64 acc[8][4])
{
    const int tid = threadIdx.x;
    const int ar  = tid >> 1, akq = (tid & 1) << 2;   // A (and NT-B) loader
    const int bk  = tid >> 5, bn  = (tid & 31) << 2;  // NN-B loader
    const int tx  = tid & 15, ty  = tid >> 4;

    const int S = K >> 3;
    float4 av, bv;

    // stage 0
    av = *(const float4*)(Ag + (size_t)ar * lda + akq);
    if (NT) bv = *(const float4*)(Bg + (size_t)ar * ldb + akq);
    else    bv = *(const float4*)(Bg + (size_t)bk * ldb + bn);
    {
        float va[4] = {av.x, av.y, av.z, av.w};
        #pragma unroll
        for (int q = 0; q < 4; q++) sAd[(akq + q) * 128 + ar] = pack2(va[q]);
        if (NT) {
            float vb[4] = {bv.x, bv.y, bv.z, bv.w};
            #pragma unroll
            for (int q = 0; q < 4; q++) sB[(akq + q) * 128 + ar] = vb[q];
        } else {
            *(float4*)&sB[bk * 128 + bn] = bv;
        }
    }
    __syncthreads();

    for (int s = 0; s < S; s++) {
        const int buf = s & 1;
        if (s + 1 < S) {
            const int k1 = (s + 1) << 3;
            av = *(const float4*)(Ag + (size_t)ar * lda + k1 + akq);
            if (NT) bv = *(const float4*)(Bg + (size_t)ar * ldb + k1 + akq);
            else    bv = *(const float4*)(Bg + (size_t)(k1 + bk) * ldb + bn);
        }
        const u64*   aBase = sAd + buf * 1024;
        const float* bBase = sB  + buf * 1024;
        #pragma unroll
        for (int kk = 0; kk < 8; kk++) {
            const u64*   aRow = aBase + kk * 128;
            const float* bRow = bBase + kk * 128;
            ulonglong2 a01 = *(const ulonglong2*)(aRow + ty * 4);
            ulonglong2 a23 = *(const ulonglong2*)(aRow + ty * 4 + 2);
            ulonglong2 a45 = *(const ulonglong2*)(aRow + 64 + ty * 4);
            ulonglong2 a67 = *(const ulonglong2*)(aRow + 64 + ty * 4 + 2);
            ulonglong2 b01 = *(const ulonglong2*)(bRow + tx * 4);
            ulonglong2 b23 = *(const ulonglong2*)(bRow + 64 + tx * 4);
            u64 a[8] = {a01.x, a01.y, a23.x, a23.y, a45.x, a45.y, a67.x, a67.y};
            u64 b[4] = {b01.x, b01.y, b23.x, b23.y};
            #pragma unroll
            for (int i = 0; i < 8; i++)
                #pragma unroll
                for (int j = 0; j < 4; j++)
                    acc[i][j] = ffma2(a[i], b[j], acc[i][j]);
        }
        if (s + 1 < S) {
            const int nb = (buf ^ 1) * 1024;
            float va[4] = {av.x, av.y, av.z, av.w};
            #pragma unroll
            for (int q = 0; q < 4; q++) sAd[nb + (akq + q) * 128 + ar] = pack2(va[q]);
            if (NT) {
                float vb[4] = {bv.x, bv.y, bv.z, bv.w};
                #pragma unroll
                for (int q = 0; q < 4; q++) sB[nb + (akq + q) * 128 + ar] = vb[q];
            } else {
                *(float4*)&sB[nb + bk * 128 + bn] = bv;
            }
        }
        __syncthreads();
    }
}

#define ROWI(i) ( ((i) < 4) ? (ty * 4 + (i)) : (64 + ty * 4 + (i) - 4) )

// ---------------- GEMM kernels ----------------------------------------------
// C[z] = A(NNODE x D) @ W[z](D x D)
__global__ __launch_bounds__(256, 2) void k_gemm_nn(const float* __restrict__ A,
                                                    const float* __restrict__ W,
                                                    float* __restrict__ C) {
    __shared__ __align__(16) u64   sAd[2048];
    __shared__ __align__(16) float sB[2048];
    int m0 = blockIdx.y * 128, n0 = blockIdx.x * 128, z = blockIdx.z;
    u64 acc[8][4];
    #pragma unroll
    for (int i = 0; i < 8; i++)
        #pragma unroll
        for (int j = 0; j < 4; j++) acc[i][j] = 0ull;
    mm128x2<false>(A + (size_t)m0 * DDIM, DDIM,
                   W + (size_t)z * DDIM * DDIM + n0, DDIM, DDIM, sAd, sB, acc);
    float* Cg = C + (size_t)z * NNODE * DDIM;
    int tx = threadIdx.x & 15, ty = threadIdx.x >> 4;
    #pragma unroll
    for (int i = 0; i < 8; i++) {
        int r = m0 + ROWI(i);
        *(float4*)&Cg[(size_t)r * DDIM + n0 + tx * 4] =
            make_float4(plo(acc[i][0]), phi(acc[i][0]), plo(acc[i][1]), phi(acc[i][1]));
        *(float4*)&Cg[(size_t)r * DDIM + n0 + 64 + tx * 4] =
            make_float4(plo(acc[i][2]), phi(acc[i][2]), plo(acc[i][3]), phi(acc[i][3]));
    }
}

// Ablk[b] = (X_b X_b^T) * sc_i * sc_j
__global__ __launch_bounds__(256, 2) void k_corr(const float* __restrict__ x,
                                                 const float* __restrict__ sc,
                                                 float* __restrict__ Ablk) {
    __shared__ __align__(16) u64   sAd[2048];
    __shared__ __align__(16) float sB[2048];
    int m0 = blockIdx.y * 128, n0 = blockIdx.x * 128, b = blockIdx.z;
    const float* base = x + (size_t)b * NPG * DDIM;
    u64 acc[8][4];
    #pragma unroll
    for (int i = 0; i < 8; i++)
        #pragma unroll
        for (int j = 0; j < 4; j++) acc[i][j] = 0ull;
    mm128x2<true>(base + (size_t)m0 * DDIM, DDIM,
                  base + (size_t)n0 * DDIM, DDIM, DDIM, sAd, sB, acc);
    int tx = threadIdx.x & 15, ty = threadIdx.x >> 4;
    const float* scb = sc + b * NPG;
    #pragma unroll
    for (int i = 0; i < 8; i++) {
        int li = m0 + ROWI(i);
        float si = scb[li];
        float* row = Ablk + ((size_t)b * NPG + li) * NPG;
        #pragma unroll
        for (int jh = 0; jh < 2; jh++) {
            int c0 = n0 + jh * 64 + tx * 4;
            float4 v;
            v.x = plo(acc[i][jh * 2 + 0]) * si * scb[c0 + 0];
            v.y = phi(acc[i][jh * 2 + 0]) * si * scb[c0 + 1];
            v.z = plo(acc[i][jh * 2 + 1]) * si * scb[c0 + 2];
            v.w = phi(acc[i][jh * 2 + 1]) * si * scb[c0 + 3];
            *(float4*)&row[c0] = v;
        }
    }
}

// Hout[b] = relu( sum_t Adj_t[b] @ G_t[b] + sum_t bias_t )
__global__ __launch_bounds__(256, 2) void k_aggr(const float* __restrict__ Adj,
                                                 const float* __restrict__ G,
                                                 const float* __restrict__ bg,
                                                 float* __restrict__ Hout) {
    __shared__ __align__(16) u64   sAd[2048];
    __shared__ __align__(16) float sB[2048];
    int m0 = blockIdx.y * 128, n0 = blockIdx.x * 128, b = blockIdx.z;
    u64 acc[8][4];
    #pragma unroll
    for (int i = 0; i < 8; i++)
        #pragma unroll
        for (int j = 0; j < 4; j++) acc[i][j] = 0ull;
    for (int t = 0; t < 3; t++) {
        const float* Ag = Adj + ((size_t)(t * BGRP + b)) * NPG * NPG + (size_t)m0 * NPG;
        const float* Bg = G + (size_t)t * NNODE * DDIM + (size_t)b * NPG * DDIM + n0;
        mm128x2<false>(Ag, NPG, Bg, DDIM, DDIM, sAd, sB, acc);
    }
    int tx = threadIdx.x & 15, ty = threadIdx.x >> 4;
    #pragma unroll
    for (int i = 0; i < 8; i++) {
        int li = m0 + ROWI(i);
        float* row = Hout + ((size_t)b * NPG + li) * DDIM;
        #pragma unroll
        for (int jh = 0; jh < 2; jh++) {
            int c0 = n0 + jh * 64 + tx * 4;
            float4 v;
            v.x = fmaxf(plo(acc[i][jh * 2 + 0]) + bg[c0 + 0] + bg[DDIM + c0 + 0] + bg[2 * DDIM + c0 + 0], 0.f);
            v.y = fmaxf(phi(acc[i][jh * 2 + 0]) + bg[c0 + 1] + bg[DDIM + c0 + 1] + bg[2 * DDIM + c0 + 1], 0.f);
            v.z = fmaxf(plo(acc[i][jh * 2 + 1]) + bg[c0 + 2] + bg[DDIM + c0 + 2] + bg[2 * DDIM + c0 + 2], 0.f);
            v.w = fmaxf(phi(acc[i][jh * 2 + 1]) + bg[c0 + 3] + bg[DDIM + c0 + 3] + bg[2 * DDIM + c0 + 3], 0.f);
            *(float4*)&row[c0] = v;
        }
    }
}

// Ablk[b] = 0.5*Ablk[b] + 0.5*sigmoid( HT_b @ Hn_b^T )
__global__ __launch_bounds__(256, 2) void k_ahat(const float* __restrict__ HT,
                                                 const float* __restrict__ Hn,
                                                 float* __restrict__ Ablk) {
    __shared__ __align__(16) u64   sAd[2048];
    __shared__ __align__(16) float sB[2048];
    int m0 = blockIdx.y * 128, n0 = blockIdx.x * 128, b = blockIdx.z;
    u64 acc[8][4];
    #pragma unroll
    for (int i = 0; i < 8; i++)
        #pragma unroll
        for (int j = 0; j < 4; j++) acc[i][j] = 0ull;
    mm128x2<true>(HT + ((size_t)b * NPG + m0) * DDIM, DDIM,
                  Hn + ((size_t)b * NPG + n0) * DDIM, DDIM, DDIM, sAd, sB, acc);
    int tx = threadIdx.x & 15, ty = threadIdx.x >> 4;
    #pragma unroll
    for (int i = 0; i < 8; i++) {
        int li = m0 + ROWI(i);
        float* row = Ablk + ((size_t)b * NPG + li) * NPG;
        #pragma unroll
        for (int jh = 0; jh < 2; jh++) {
            int c0 = n0 + jh * 64 + tx * 4;
            float4 old = *(const float4*)&row[c0];
            float4 v;
            v.x = 0.5f * old.x + 0.5f / (1.0f + expf(-plo(acc[i][jh * 2 + 0])));
            v.y = 0.5f * old.y + 0.5f / (1.0f + expf(-phi(acc[i][jh * 2 + 0])));
            v.z = 0.5f * old.z + 0.5f / (1.0f + expf(-plo(acc[i][jh * 2 + 1])));
            v.w = 0.5f * old.w + 0.5f / (1.0f + expf(-phi(acc[i][jh * 2 + 1])));
            *(float4*)&row[c0] = v;
        }
    }
}

// ---------------- small kernels ---------------------------------------------
__global__ void k_mask_detect(const unsigned char* __restrict__ em,
                              const unsigned char* __restrict__ pm) {
    __shared__ int nz[4];
    if (threadIdx.x < 4) nz[threadIdx.x] = 0;
    __syncthreads();
    int loc[4] = {0, 0, 0, 0};
    for (int i = threadIdx.x; i < NMASK; i += 256) {
        if (em[i]) loc[i & 3]++;
        if (pm[i]) loc[i & 3]++;
    }
    #pragma unroll
    for (int j = 0; j < 4; j++) if (loc[j]) atomicAdd(&nz[j], loc[j]);
    __syncthreads();
    if (threadIdx.x == 0) {
        int mode;
        if (nz[1] > 0) mode = 0;
        else if (nz[0] > 0) mode = 1;
        else mode = 2;
        g_mask_mode = mode;
    }
}

__global__ void k_mask_decode(const unsigned char* __restrict__ em,
                              const unsigned char* __restrict__ pm,
                              float* __restrict__ emf, float* __restrict__ pmf) {
    int i = blockIdx.x * blockDim.x + threadIdx.x;
    if (i >= NMASK) return;
    int mode = g_mask_mode;
    float e, p;
    if (mode == 0) {
        e = em[i] ? 1.f : 0.f;
        p = pm[i] ? 1.f : 0.f;
    } else if (mode == 1) {
        e = ((const int*)em)[i] ? 1.f : 0.f;
        p = ((const int*)pm)[i] ? 1.f : 0.f;
    } else {
        e = (((const float*)em)[i] != 0.f) ? 1.f : 0.f;
        p = (((const float*)pm)[i] != 0.f) ? 1.f : 0.f;
    }
    emf[i] = e; pmf[i] = p;
}

__global__ void k_rownorm(const float* __restrict__ x, float* __restrict__ nrm,
                          float* __restrict__ rinv) {
    int warp = (blockIdx.x * blockDim.x + threadIdx.x) >> 5;
    int lane = threadIdx.x & 31;
    if (warp >= NNODE) return;
    const float* r = x + (size_t)warp * DDIM;
    float s = 0.f;
    for (int j = lane; j < DDIM; j += 32) { float v = r[j]; s += v * v; }
    #pragma unroll
    for (int o = 16; o; o >>= 1) s += __shfl_xor_sync(0xffffffffu, s, o);
    if (!lane) { float n = sqrtf(s); nrm[warp] = n; rinv[warp] = 1.0f / n; }
}

__global__ void k_colsum(const float* __restrict__ x, const float* __restrict__ rinv,
                         float* __restrict__ svec) {
    int d = threadIdx.x;
    int r0 = blockIdx.x * 32;
    float acc = 0.f;
    for (int r = r0; r < r0 + 32; r++)
        acc += x[(size_t)r * DDIM + d] * rinv[r];
    atomicAdd(&svec[d], acc);
}

__global__ void k_scale(const float* __restrict__ x, const float* __restrict__ rinv,
                        const float* __restrict__ svec, float* __restrict__ sc) {
    int warp = (blockIdx.x * blockDim.x + threadIdx.x) >> 5;
    int lane = threadIdx.x & 31;
    if (warp >= NNODE) return;
    const float* r = x + (size_t)warp * DDIM;
    float dot = 0.f;
    for (int j = lane; j < DDIM; j += 32) dot += r[j] * svec[j];
    #pragma unroll
    for (int o = 16; o; o >>= 1) dot += __shfl_xor_sync(0xffffffffu, dot, o);
    if (!lane) {
        float rowsum = dot * rinv[warp];
        sc[warp] = rsqrtf(fabsf(rowsum) + ZERO_EPS) * rinv[warp];
    }
}

__global__ void k_scatter_w(const int* __restrict__ ei, const float* __restrict__ ew,
                            float* __restrict__ Adj) {
    int e = blockIdx.x * blockDim.x + threadIdx.x;
    if (e >= NEDGE) return;
    int src = ei[e], dst = ei[NEDGE + e];
    int b = src >> 8, sl = src & 255, dl = dst & 255;
    atomicAdd(&Adj[(((size_t)b << 8) + dl) * NPG + sl], ew[e]);
}

__global__ void k_scatter_A(const int* __restrict__ ei, const float* __restrict__ Ablk,
                            float* __restrict__ Adj) {
    int e = blockIdx.x * blockDim.x + threadIdx.x;
    if (e >= NEDGE) return;
    int src = ei[e], dst = ei[NEDGE + e];
    int b = src >> 8, sl = src & 255, dl = dst & 255;
    float w = Ablk[(((size_t)b << 8) + sl) * NPG + dl];
    atomicAdd(&Adj[(((size_t)b << 8) + dl) * NPG + sl], w);
}

// ---------------- final maps ------------------------------------------------
__global__ __launch_bounds__(256) void k_final(const float* __restrict__ Ablk,
                                               const float* __restrict__ emf,
                                               const float* __restrict__ pmf,
                                               float* __restrict__ out) {
    int b = blockIdx.x;
    __shared__ float ems[NPG], pms[NPG];
    __shared__ float me[NPG], mp[NPG];
    __shared__ float red[256];
    int t = threadIdx.x;
    ems[t] = emf[b * NPG + t];
    pms[t] = pmf[b * NPG + t];
    __syncthreads();
    int warp = t >> 5, lane = t & 31;
    for (int r = warp; r < NPG; r += 8) {
        const float* row = Ablk + ((size_t)b * NPG + r) * NPG;
        float s = 0.f, es = 0.f, ps = 0.f;
        for (int j = lane; j < NPG; j += 32) {
            float a = row[j];
            s += a; es += a * ems[j]; ps += a * pms[j];
        }
        #pragma unroll
        for (int o = 16; o; o >>= 1) {
            s  += __shfl_xor_sync(0xffffffffu, s, o);
            es += __shfl_xor_sync(0xffffffffu, es, o);
            ps += __shfl_xor_sync(0xffffffffu, ps, o);
        }
        if (!lane) { me[r] = s - ps; mp[r] = s - es; }
    }
    __syncthreads();
    for (int pass = 0; pass < 2; pass++) {
        float v = pass ? mp[t] : me[t];
        red[t] = v; __syncthreads();
        for (int s2 = 128; s2; s2 >>= 1) {
            if (t < s2) red[t] = fminf(red[t], red[t + s2]);
            __syncthreads();
        }
        float mn = red[0]; __syncthreads();
        red[t] = v; __syncthreads();
        for (int s2 = 128; s2; s2 >>= 1) {
            if (t < s2) red[t] = fmaxf(red[t], red[t + s2]);
            __syncthreads();
        }
        float mx = red[0]; __syncthreads();
        float u = (v - mn) / (mx - mn + ZERO_EPS);
        red[t] = u; __syncthreads();
        for (int s2 = 128; s2; s2 >>= 1) {
            if (t < s2) red[t] += red[t + s2];
            __syncthreads();
        }
        float sm = red[0]; __syncthreads();
        out[pass * (BGRP * NPG) + b * NPG + t] = u / (sm + ZERO_EPS);
    }
}

// ---------------- host ------------------------------------------------------
extern "C" void kernel_launch(void* const* d_in, const int* in_sizes, int n_in,
                              void* d_out, int out_size) {
    const float*     x    = (const float*)d_in[0];
    const int*       ei_e = (const int*)d_in[1];
    const float*     ew_e = (const float*)d_in[2];
    const int*       ei_p = (const int*)d_in[3];
    const float*     ew_p = (const float*)d_in[4];
    const int*       ei_o = (const int*)d_in[5];
    const float*     ew_o = (const float*)d_in[6];
    const unsigned char* em = (const unsigned char*)d_in[7];
    const unsigned char* pm = (const unsigned char*)d_in[8];
    const float*     Wg   = (const float*)d_in[9];
    const float*     bg   = (const float*)d_in[10];
    const float*     Td   = (const float*)d_in[11];
    float* out = (float*)d_out;

    float *H0, *H1, *G, *HT, *Ablk, *Adj, *nrm, *rinv, *sc, *svec, *emf, *pmf;
    cudaGetSymbolAddress((void**)&H0,   g_H0);
    cudaGetSymbolAddress((void**)&H1,   g_H1);
    cudaGetSymbolAddress((void**)&G,    g_G);
    cudaGetSymbolAddress((void**)&HT,   g_HT);
    cudaGetSymbolAddress((void**)&Ablk, g_Ablk);
    cudaGetSymbolAddress((void**)&Adj,  g_Adj);
    cudaGetSymbolAddress((void**)&nrm,  g_nrm);
    cudaGetSymbolAddress((void**)&rinv, g_rinv);
    cudaGetSymbolAddress((void**)&sc,   g_sc);
    cudaGetSymbolAddress((void**)&svec, g_svec);
    cudaGetSymbolAddress((void**)&emf,  g_emf);
    cudaGetSymbolAddress((void**)&pmf,  g_pmf);

    const size_t ADJ1 = (size_t)BGRP * NPG * NPG;

    // masks
    k_mask_detect<<<1, 256>>>(em, pm);
    k_mask_decode<<<NMASK / 256, 256>>>(em, pm, emf, pmf);

    // prologue
    cudaMemsetAsync(Adj, 0, 3 * ADJ1 * sizeof(float));
    cudaMemsetAsync(svec, 0, DDIM * sizeof(float));
    k_rownorm<<<NNODE / 8, 256>>>(x, nrm, rinv);
    k_colsum<<<256, 256>>>(x, rinv, svec);
    k_scale<<<NNODE / 8, 256>>>(x, rinv, svec, sc);
    k_corr<<<dim3(2, 2, BGRP), 256>>>(x, sc, Ablk);

    // layer-0 adjacency
    k_scatter_w<<<NEDGE / 256, 256>>>(ei_e, ew_e, Adj);
    k_scatter_w<<<NEDGE / 256, 256>>>(ei_p, ew_p, Adj + ADJ1);
    k_scatter_w<<<NEDGE / 256, 256>>>(ei_o, ew_o, Adj + 2 * ADJ1);

    // layer 0
    k_gemm_nn<<<dim3(2, 64, 3), 256>>>(x, Wg, G);
    k_aggr<<<dim3(2, 2, BGRP), 256>>>(Adj, G, bg, H0);
    k_gemm_nn<<<dim3(2, 64, 1), 256>>>(H0, Td, HT);
    k_ahat<<<dim3(2, 2, BGRP), 256>>>(HT, H0, Ablk);

    // layer-1 adjacency
    cudaMemsetAsync(Adj, 0, 3 * ADJ1 * sizeof(float));
    k_scatter_A<<<NEDGE / 256, 256>>>(ei_e, Ablk, Adj);
    k_scatter_A<<<NEDGE / 256, 256>>>(ei_p, Ablk, Adj + ADJ1);
    k_scatter_A<<<NEDGE / 256, 256>>>(ei_o, Ablk, Adj + 2 * ADJ1);

    // layer 1
    k_gemm_nn<<<dim3(2, 64, 3), 256>>>(H0, Wg + 3 * DDIM * DDIM, G);
    k_aggr<<<dim3(2, 2, BGRP), 256>>>(Adj, G, bg + 3 * DDIM, H1);
    k_gemm_nn<<<dim3(2, 64, 1), 256>>>(H1, Td + DDIM * DDIM, HT);
    k_ahat<<<dim3(2, 2, BGRP), 256>>>(HT, H1, Ablk);

    // final maps
    k_final<<<BGRP, 256>>>(Ablk, emf, pmf, out);
}

// round 8
// speedup vs baseline: 1.3959x; 1.2038x over previous
#include <cuda_runtime.h>
#include <math.h>
#include <stdint.h>

#define NNODE 8192
#define DDIM  256
#define NPG   256
#define BGRP  32
#define NEDGE 131072
#define NMASK (BGRP * NPG)
#define ZERO_EPS 1e-8f
#define PLANE_H (NNODE * DDIM)

// ---------------- scratch ----------------------------------------------------
__device__ float g_H0[NNODE * DDIM];
__device__ float g_H1[NNODE * DDIM];
__device__ float g_G[3 * NNODE * DDIM];
__device__ float g_P[3 * NNODE * DDIM];
__device__ float g_HT[NNODE * DDIM];
__device__ float g_Ablk[BGRP * NPG * NPG];
__device__ float g_Adj[3 * BGRP * NPG * NPG];
__device__ float g_nrm[NNODE];
__device__ float g_rinv[NNODE];
__device__ float g_sc[NNODE];
__device__ float g_svec[DDIM];
__device__ float g_emf[NMASK];
__device__ float g_pmf[NMASK];
__device__ int   g_mask_mode;

// ---------------- tf32 helpers ----------------------------------------------
__device__ __forceinline__ float tf32_rna(float x) {
    uint32_t u;
    asm("cvt.rna.tf32.f32 %0, %1;" : "=r"(u) : "f"(x));
    return __uint_as_float(u);
}

__device__ __forceinline__ void mma8(float c[4], const float a[4], float b0, float b1) {
    asm volatile("mma.sync.aligned.m16n8k8.row.col.f32.tf32.tf32.f32 "
        "{%0,%1,%2,%3}, {%4,%5,%6,%7}, {%8,%9}, {%0,%1,%2,%3};"
        : "+f"(c[0]), "+f"(c[1]), "+f"(c[2]), "+f"(c[3])
        : "r"(__float_as_uint(a[0])), "r"(__float_as_uint(a[1])),
          "r"(__float_as_uint(a[2])), "r"(__float_as_uint(a[3])),
          "r"(__float_as_uint(b0)),  "r"(__float_as_uint(b1)));
}

// ---------------- 128x128xK(=256) 3xTF32 mainloop, single-buffered ----------
// Block = 256 thr = 8 warps in 4(M)x2(N); warp tile 32x64; mma m16n8k8.
// A row-major MxK (Ag at tile row 0), lda.
// NT=false: B row-major KxN (Bg at tile col 0), ldb.
// NT=true : B row-major NxK (Bg at tile row 0), ldb -> computes A @ B^T.
// smem (floats): sAH [128][20], sAL [128][20];
//   NN: sBH/sBL [16][136];  NT: sBH/sBL [128][20].   total <= 40KB.
#define AIDX(r,k) ((r)*20 + (k))
#define BNNI(k,n) ((k)*136 + (n))
#define BNTI(n,k) ((n)*20 + (k))

template<bool NT>
__device__ __forceinline__ void mma_loop(const float* __restrict__ Ag, int lda,
                                         const float* __restrict__ Bg, int ldb,
                                         float* __restrict__ smem,
                                         float (*acc)[8][4])
{
    const int tid  = threadIdx.x;
    const int lane = tid & 31;
    const int warp = tid >> 5;
    const int gid  = lane >> 2, tig = lane & 3;
    const int wm   = (warp & 3) * 32, wn = (warp >> 2) * 64;
    const int ar   = tid >> 2, akq = (tid & 3) << 2;   // A / NT-B loader
    const int bk   = tid >> 5, bn4 = (tid & 31) << 2;  // NN-B loader

    float* sAH = smem;
    float* sAL = smem + 2560;
    float* sBH = smem + 5120;
    float* sBL = sBH + (NT ? 2560 : 2176);

    for (int s = 0; s < 16; s++) {
        const int s1 = s * 16;
        // ---- prefetch into registers (latency overlapped with other CTA) ----
        float4 pa0 = *(const float4*)(Ag + (size_t)ar * lda + s1 + akq);
        float4 pa1 = *(const float4*)(Ag + (size_t)(ar + 64) * lda + s1 + akq);
        float4 pb0, pb1;
        if (NT) {
            pb0 = *(const float4*)(Bg + (size_t)ar * ldb + s1 + akq);
            pb1 = *(const float4*)(Bg + (size_t)(ar + 64) * ldb + s1 + akq);
        } else {
            pb0 = *(const float4*)(Bg + (size_t)(s1 + bk) * ldb + bn4);
            pb1 = *(const float4*)(Bg + (size_t)(s1 + bk + 8) * ldb + bn4);
        }
        __syncthreads();   // previous stage's compute fully consumed smem
        {
            float va[8] = {pa0.x, pa0.y, pa0.z, pa0.w, pa1.x, pa1.y, pa1.z, pa1.w};
            #pragma unroll
            for (int i = 0; i < 8; i++) {
                int r = (i < 4) ? ar : ar + 64;
                int k = akq + (i & 3);
                float hi = tf32_rna(va[i]);
                sAH[AIDX(r, k)] = hi;
                sAL[AIDX(r, k)] = tf32_rna(va[i] - hi);
            }
            float vb[8] = {pb0.x, pb0.y, pb0.z, pb0.w, pb1.x, pb1.y, pb1.z, pb1.w};
            #pragma unroll
            for (int i = 0; i < 8; i++) {
                float hi = tf32_rna(vb[i]);
                float lo = tf32_rna(vb[i] - hi);
                if (NT) {
                    int r = (i < 4) ? ar : ar + 64;
                    int k = akq + (i & 3);
                    sBH[BNTI(r, k)] = hi; sBL[BNTI(r, k)] = lo;
                } else {
                    int k = (i < 4) ? bk : bk + 8;
                    int n = bn4 + (i & 3);
                    sBH[BNNI(k, n)] = hi; sBL[BNNI(k, n)] = lo;
                }
            }
        }
        __syncthreads();
        // ---- compute ----
        #pragma unroll
        for (int kg = 0; kg < 2; kg++) {
            const int k0 = kg * 8 + tig;
            float ah[2][4], al[2][4];
            #pragma unroll
            for (int mt = 0; mt < 2; mt++) {
                const int r0 = wm + mt * 16 + gid;
                ah[mt][0] = sAH[AIDX(r0,     k0)];
                ah[mt][1] = sAH[AIDX(r0 + 8, k0)];
                ah[mt][2] = sAH[AIDX(r0,     k0 + 4)];
                ah[mt][3] = sAH[AIDX(r0 + 8, k0 + 4)];
                al[mt][0] = sAL[AIDX(r0,     k0)];
                al[mt][1] = sAL[AIDX(r0 + 8, k0)];
                al[mt][2] = sAL[AIDX(r0,     k0 + 4)];
                al[mt][3] = sAL[AIDX(r0 + 8, k0 + 4)];
            }
            #pragma unroll
            for (int nt = 0; nt < 8; nt++) {
                const int cn = wn + nt * 8 + gid;
                float bh0, bh1, bl0, bl1;
                if (NT) {
                    bh0 = sBH[BNTI(cn, k0)];
                    bh1 = sBH[BNTI(cn, k0 + 4)];
                    bl0 = sBL[BNTI(cn, k0)];
                    bl1 = sBL[BNTI(cn, k0 + 4)];
                } else {
                    bh0 = sBH[BNNI(k0,     cn)];
                    bh1 = sBH[BNNI(k0 + 4, cn)];
                    bl0 = sBL[BNNI(k0,     cn)];
                    bl1 = sBL[BNNI(k0 + 4, cn)];
                }
                #pragma unroll
                for (int mt = 0; mt < 2; mt++) {
                    mma8(acc[mt][nt], ah[mt], bh0, bh1);
                    mma8(acc[mt][nt], al[mt], bh0, bh1);
                    mma8(acc[mt][nt], ah[mt], bl0, bl1);
                }
            }
        }
    }
    __syncthreads();
}

#define SMEM_FLOATS 10240   // 40KB

// ---------------- GEMM kernels ----------------------------------------------
// C[z] = A(NNODE x D) @ W[z](D x D)
__global__ __launch_bounds__(256, 2) void k_gemm_nn(const float* __restrict__ A,
                                                    const float* __restrict__ W,
                                                    float* __restrict__ C) {
    __shared__ __align__(16) float sm[SMEM_FLOATS];
    const int m0 = blockIdx.y * 128, n0 = blockIdx.x * 128, z = blockIdx.z;
    float acc[2][8][4];
    #pragma unroll
    for (int i = 0; i < 2; i++)
        #pragma unroll
        for (int j = 0; j < 8; j++)
            #pragma unroll
            for (int q = 0; q < 4; q++) acc[i][j][q] = 0.f;
    mma_loop<false>(A + (size_t)m0 * DDIM, DDIM,
                    W + (size_t)z * DDIM * DDIM + n0, DDIM, sm, acc);
    float* Cg = C + (size_t)z * NNODE * DDIM;
    const int lane = threadIdx.x & 31, warp = threadIdx.x >> 5;
    const int gid = lane >> 2, tig = lane & 3;
    const int wm = (warp & 3) * 32, wn = (warp >> 2) * 64;
    #pragma unroll
    for (int mt = 0; mt < 2; mt++)
        #pragma unroll
        for (int nt = 0; nt < 8; nt++) {
            int r = m0 + wm + mt * 16 + gid;
            int c = n0 + wn + nt * 8 + 2 * tig;
            *(float2*)&Cg[(size_t)r * DDIM + c] = make_float2(acc[mt][nt][0], acc[mt][nt][1]);
            *(float2*)&Cg[(size_t)(r + 8) * DDIM + c] = make_float2(acc[mt][nt][2], acc[mt][nt][3]);
        }
}

// Ablk[b] = (X_b X_b^T) * sc_i * sc_j
__global__ __launch_bounds__(256, 2) void k_corr(const float* __restrict__ x,
                                                 const float* __restrict__ sc,
                                                 float* __restrict__ Ablk) {
    __shared__ __align__(16) float sm[SMEM_FLOATS];
    const int m0 = blockIdx.y * 128, n0 = blockIdx.x * 128, b = blockIdx.z;
    const float* base = x + (size_t)b * NPG * DDIM;
    float acc[2][8][4];
    #pragma unroll
    for (int i = 0; i < 2; i++)
        #pragma unroll
        for (int j = 0; j < 8; j++)
            #pragma unroll
            for (int q = 0; q < 4; q++) acc[i][j][q] = 0.f;
    mma_loop<true>(base + (size_t)m0 * DDIM, DDIM,
                   base + (size_t)n0 * DDIM, DDIM, sm, acc);
    const int lane = threadIdx.x & 31, warp = threadIdx.x >> 5;
    const int gid = lane >> 2, tig = lane & 3;
    const int wm = (warp & 3) * 32, wn = (warp >> 2) * 64;
    const float* scb = sc + b * NPG;
    #pragma unroll
    for (int mt = 0; mt < 2; mt++)
        #pragma unroll
        for (int nt = 0; nt < 8; nt++) {
            int li = m0 + wm + mt * 16 + gid;
            int lj = n0 + wn + nt * 8 + 2 * tig;
            float s0 = scb[li], s1 = scb[li + 8];
            float c0 = scb[lj], c1 = scb[lj + 1];
            float* row0 = Ablk + ((size_t)b * NPG + li) * NPG;
            float* row1 = Ablk + ((size_t)b * NPG + li + 8) * NPG;
            *(float2*)&row0[lj] = make_float2(acc[mt][nt][0] * s0 * c0, acc[mt][nt][1] * s0 * c1);
            *(float2*)&row1[lj] = make_float2(acc[mt][nt][2] * s1 * c0, acc[mt][nt][3] * s1 * c1);
        }
}

// P[t][b] = Adj_t[b] @ G_t[b]   (partials; full-chip grid z = t*32+b)
__global__ __launch_bounds__(256, 2) void k_aggr_part(const float* __restrict__ Adj,
                                                      const float* __restrict__ G,
                                                      float* __restrict__ P) {
    __shared__ __align__(16) float sm[SMEM_FLOATS];
    const int m0 = blockIdx.y * 128, n0 = blockIdx.x * 128;
    const int z = blockIdx.z, b = z & 31, t = z >> 5;
    float acc[2][8][4];
    #pragma unroll
    for (int i = 0; i < 2; i++)
        #pragma unroll
        for (int j = 0; j < 8; j++)
            #pragma unroll
            for (int q = 0; q < 4; q++) acc[i][j][q] = 0.f;
    const float* Ag = Adj + ((size_t)(t * BGRP + b)) * NPG * NPG + (size_t)m0 * NPG;
    const float* Bg = G + (size_t)t * PLANE_H + (size_t)b * NPG * DDIM + n0;
    mma_loop<false>(Ag, NPG, Bg, DDIM, sm, acc);
    float* Pp = P + (size_t)t * PLANE_H + (size_t)b * NPG * DDIM;
    const int lane = threadIdx.x & 31, warp = threadIdx.x >> 5;
    const int gid = lane >> 2, tig = lane & 3;
    const int wm = (warp & 3) * 32, wn = (warp >> 2) * 64;
    #pragma unroll
    for (int mt = 0; mt < 2; mt++)
        #pragma unroll
        for (int nt = 0; nt < 8; nt++) {
            int r = m0 + wm + mt * 16 + gid;
            int c = n0 + wn + nt * 8 + 2 * tig;
            *(float2*)&Pp[(size_t)r * DDIM + c] = make_float2(acc[mt][nt][0], acc[mt][nt][1]);
            *(float2*)&Pp[(size_t)(r + 8) * DDIM + c] = make_float2(acc[mt][nt][2], acc[mt][nt][3]);
        }
}

// H = relu(P0 + P1 + P2 + biassum)
__global__ void k_red(const float* __restrict__ P, const float* __restrict__ bgl,
                      float* __restrict__ H) {
    int i = blockIdx.x * blockDim.x + threadIdx.x;
    if (i >= PLANE_H) return;
    int c = i & 255;
    float bias = bgl[c] + bgl[DDIM + c] + bgl[2 * DDIM + c];
    float v = P[i] + P[i + PLANE_H] + P[i + 2 * PLANE_H] + bias;
    H[i] = fmaxf(v, 0.f);
}

// Ablk[b] = 0.5*Ablk[b] + 0.5*sigmoid( HT_b @ Hn_b^T )
__global__ __launch_bounds__(256, 2) void k_ahat(const float* __restrict__ HT,
                                                 const float* __restrict__ Hn,
                                                 float* __restrict__ Ablk) {
    __shared__ __align__(16) float sm[SMEM_FLOATS];
    const int m0 = blockIdx.y * 128, n0 = blockIdx.x * 128, b = blockIdx.z;
    float acc[2][8][4];
    #pragma unroll
    for (int i = 0; i < 2; i++)
        #pragma unroll
        for (int j = 0; j < 8; j++)
            #pragma unroll
            for (int q = 0; q < 4; q++) acc[i][j][q] = 0.f;
    mma_loop<true>(HT + ((size_t)b * NPG + m0) * DDIM, DDIM,
                   Hn + ((size_t)b * NPG + n0) * DDIM, DDIM, sm, acc);
    const int lane = threadIdx.x & 31, warp = threadIdx.x >> 5;
    const int gid = lane >> 2, tig = lane & 3;
    const int wm = (warp & 3) * 32, wn = (warp >> 2) * 64;
    #pragma unroll
    for (int mt = 0; mt < 2; mt++)
        #pragma unroll
        for (int nt = 0; nt < 8; nt++) {
            int li = m0 + wm + mt * 16 + gid;
            int lj = n0 + wn + nt * 8 + 2 * tig;
            float* row0 = Ablk + ((size_t)b * NPG + li) * NPG;
            float* row1 = Ablk + ((size_t)b * NPG + li + 8) * NPG;
            float2 o0 = *(const float2*)&row0[lj];
            float2 o1 = *(const float2*)&row1[lj];
            float2 v0, v1;
            v0.x = 0.5f * o0.x + 0.5f / (1.0f + expf(-acc[mt][nt][0]));
            v0.y = 0.5f * o0.y + 0.5f / (1.0f + expf(-acc[mt][nt][1]));
            v1.x = 0.5f * o1.x + 0.5f / (1.0f + expf(-acc[mt][nt][2]));
            v1.y = 0.5f * o1.y + 0.5f / (1.0f + expf(-acc[mt][nt][3]));
            *(float2*)&row0[lj] = v0;
            *(float2*)&row1[lj] = v1;
        }
}

// ---------------- small kernels ---------------------------------------------
__global__ void k_mask_detect(const unsigned char* __restrict__ em,
                              const unsigned char* __restrict__ pm) {
    __shared__ int nz[4];
    if (threadIdx.x < 4) nz[threadIdx.x] = 0;
    __syncthreads();
    int loc[4] = {0, 0, 0, 0};
    for (int i = threadIdx.x; i < NMASK; i += 256) {
        if (em[i]) loc[i & 3]++;
        if (pm[i]) loc[i & 3]++;
    }
    #pragma unroll
    for (int j = 0; j < 4; j++) if (loc[j]) atomicAdd(&nz[j], loc[j]);
    __syncthreads();
    if (threadIdx.x == 0) {
        int mode;
        if (nz[1] > 0) mode = 0;
        else if (nz[0] > 0) mode = 1;
        else mode = 2;
        g_mask_mode = mode;
    }
}

__global__ void k_mask_decode(const unsigned char* __restrict__ em,
                              const unsigned char* __restrict__ pm,
                              float* __restrict__ emf, float* __restrict__ pmf) {
    int i = blockIdx.x * blockDim.x + threadIdx.x;
    if (i >= NMASK) return;
    int mode = g_mask_mode;
    float e, p;
    if (mode == 0) { e = em[i] ? 1.f : 0.f; p = pm[i] ? 1.f : 0.f; }
    else if (mode == 1) { e = ((const int*)em)[i] ? 1.f : 0.f; p = ((const int*)pm)[i] ? 1.f : 0.f; }
    else { e = (((const float*)em)[i] != 0.f) ? 1.f : 0.f; p = (((const float*)pm)[i] != 0.f) ? 1.f : 0.f; }
    emf[i] = e; pmf[i] = p;
}

__global__ void k_rownorm(const float* __restrict__ x, float* __restrict__ nrm,
                          float* __restrict__ rinv) {
    int warp = (blockIdx.x * blockDim.x + threadIdx.x) >> 5;
    int lane = threadIdx.x & 31;
    if (warp >= NNODE) return;
    const float* r = x + (size_t)warp * DDIM;
    float s = 0.f;
    for (int j = lane; j < DDIM; j += 32) { float v = r[j]; s += v * v; }
    #pragma unroll
    for (int o = 16; o; o >>= 1) s += __shfl_xor_sync(0xffffffffu, s, o);
    if (!lane) { float n = sqrtf(s); nrm[warp] = n; rinv[warp] = 1.0f / n; }
}

__global__ void k_colsum(const float* __restrict__ x, const float* __restrict__ rinv,
                         float* __restrict__ svec) {
    int d = threadIdx.x;
    int r0 = blockIdx.x * 32;
    float acc = 0.f;
    for (int r = r0; r < r0 + 32; r++)
        acc += x[(size_t)r * DDIM + d] * rinv[r];
    atomicAdd(&svec[d], acc);
}

__global__ void k_scale(const float* __restrict__ x, const float* __restrict__ rinv,
                        const float* __restrict__ svec, float* __restrict__ sc) {
    int warp = (blockIdx.x * blockDim.x + threadIdx.x) >> 5;
    int lane = threadIdx.x & 31;
    if (warp >= NNODE) return;
    const float* r = x + (size_t)warp * DDIM;
    float dot = 0.f;
    for (int j = lane; j < DDIM; j += 32) dot += r[j] * svec[j];
    #pragma unroll
    for (int o = 16; o; o >>= 1) dot += __shfl_xor_sync(0xffffffffu, dot, o);
    if (!lane) {
        float rowsum = dot * rinv[warp];
        sc[warp] = rsqrtf(fabsf(rowsum) + ZERO_EPS) * rinv[warp];
    }
}

__global__ void k_scatter_w(const int* __restrict__ ei, const float* __restrict__ ew,
                            float* __restrict__ Adj) {
    int e = blockIdx.x * blockDim.x + threadIdx.x;
    if (e >= NEDGE) return;
    int src = ei[e], dst = ei[NEDGE + e];
    int b = src >> 8, sl = src & 255, dl = dst & 255;
    atomicAdd(&Adj[(((size_t)b << 8) + dl) * NPG + sl], ew[e]);
}

__global__ void k_scatter_A(const int* __restrict__ ei, const float* __restrict__ Ablk,
                            float* __restrict__ Adj) {
    int e = blockIdx.x * blockDim.x + threadIdx.x;
    if (e >= NEDGE) return;
    int src = ei[e], dst = ei[NEDGE + e];
    int b = src >> 8, sl = src & 255, dl = dst & 255;
    float w = Ablk[(((size_t)b << 8) + sl) * NPG + dl];
    atomicAdd(&Adj[(((size_t)b << 8) + dl) * NPG + sl], w);
}

// ---------------- final maps ------------------------------------------------
__global__ __launch_bounds__(256) void k_final(const float* __restrict__ Ablk,
                                               const float* __restrict__ emf,
                                               const float* __restrict__ pmf,
                                               float* __restrict__ out) {
    int b = blockIdx.x;
    __shared__ float ems[NPG], pms[NPG];
    __shared__ float me[NPG], mp[NPG];
    __shared__ float red[256];
    int t = threadIdx.x;
    ems[t] = emf[b * NPG + t];
    pms[t] = pmf[b * NPG + t];
    __syncthreads();
    int warp = t >> 5, lane = t & 31;
    for (int r = warp; r < NPG; r += 8) {
        const float* row = Ablk + ((size_t)b * NPG + r) * NPG;
        float s = 0.f, es = 0.f, ps = 0.f;
        for (int j = lane; j < NPG; j += 32) {
            float a = row[j];
            s += a; es += a * ems[j]; ps += a * pms[j];
        }
        #pragma unroll
        for (int o = 16; o; o >>= 1) {
            s  += __shfl_xor_sync(0xffffffffu, s, o);
            es += __shfl_xor_sync(0xffffffffu, es, o);
            ps += __shfl_xor_sync(0xffffffffu, ps, o);
        }
        if (!lane) { me[r] = s - ps; mp[r] = s - es; }
    }
    __syncthreads();
    for (int pass = 0; pass < 2; pass++) {
        float v = pass ? mp[t] : me[t];
        red[t] = v; __syncthreads();
        for (int s2 = 128; s2; s2 >>= 1) {
            if (t < s2) red[t] = fminf(red[t], red[t + s2]);
            __syncthreads();
        }
        float mn = red[0]; __syncthreads();
        red[t] = v; __syncthreads();
        for (int s2 = 128; s2; s2 >>= 1) {
            if (t < s2) red[t] = fmaxf(red[t], red[t + s2]);
            __syncthreads();
        }
        float mx = red[0]; __syncthreads();
        float u = (v - mn) / (mx - mn + ZERO_EPS);
        red[t] = u; __syncthreads();
        for (int s2 = 128; s2; s2 >>= 1) {
            if (t < s2) red[t] += red[t + s2];
            __syncthreads();
        }
        float sm = red[0]; __syncthreads();
        out[pass * (BGRP * NPG) + b * NPG + t] = u / (sm + ZERO_EPS);
    }
}

// ---------------- host ------------------------------------------------------
extern "C" void kernel_launch(void* const* d_in, const int* in_sizes, int n_in,
                              void* d_out, int out_size) {
    const float*     x    = (const float*)d_in[0];
    const int*       ei_e = (const int*)d_in[1];
    const float*     ew_e = (const float*)d_in[2];
    const int*       ei_p = (const int*)d_in[3];
    const float*     ew_p = (const float*)d_in[4];
    const int*       ei_o = (const int*)d_in[5];
    const float*     ew_o = (const float*)d_in[6];
    const unsigned char* em = (const unsigned char*)d_in[7];
    const unsigned char* pm = (const unsigned char*)d_in[8];
    const float*     Wg   = (const float*)d_in[9];
    const float*     bg   = (const float*)d_in[10];
    const float*     Td   = (const float*)d_in[11];
    float* out = (float*)d_out;

    float *H0, *H1, *G, *P, *HT, *Ablk, *Adj, *nrm, *rinv, *sc, *svec, *emf, *pmf;
    cudaGetSymbolAddress((void**)&H0,   g_H0);
    cudaGetSymbolAddress((void**)&H1,   g_H1);
    cudaGetSymbolAddress((void**)&G,    g_G);
    cudaGetSymbolAddress((void**)&P,    g_P);
    cudaGetSymbolAddress((void**)&HT,   g_HT);
    cudaGetSymbolAddress((void**)&Ablk, g_Ablk);
    cudaGetSymbolAddress((void**)&Adj,  g_Adj);
    cudaGetSymbolAddress((void**)&nrm,  g_nrm);
    cudaGetSymbolAddress((void**)&rinv, g_rinv);
    cudaGetSymbolAddress((void**)&sc,   g_sc);
    cudaGetSymbolAddress((void**)&svec, g_svec);
    cudaGetSymbolAddress((void**)&emf,  g_emf);
    cudaGetSymbolAddress((void**)&pmf,  g_pmf);

    const size_t ADJ1 = (size_t)BGRP * NPG * NPG;

    // masks + prologue
    k_mask_detect<<<1, 256>>>(em, pm);
    k_mask_decode<<<NMASK / 256, 256>>>(em, pm, emf, pmf);
    cudaMemsetAsync(Adj, 0, 3 * ADJ1 * sizeof(float));
    cudaMemsetAsync(svec, 0, DDIM * sizeof(float));
    k_rownorm<<<NNODE / 8, 256>>>(x, nrm, rinv);
    k_colsum<<<256, 256>>>(x, rinv, svec);
    k_scale<<<NNODE / 8, 256>>>(x, rinv, svec, sc);
    k_corr<<<dim3(2, 2, BGRP), 256>>>(x, sc, Ablk);

    // layer-0 adjacency
    k_scatter_w<<<NEDGE / 256, 256>>>(ei_e, ew_e, Adj);
    k_scatter_w<<<NEDGE / 256, 256>>>(ei_p, ew_p, Adj + ADJ1);
    k_scatter_w<<<NEDGE / 256, 256>>>(ei_o, ew_o, Adj + 2 * ADJ1);

    // layer 0
    k_gemm_nn<<<dim3(2, 64, 3), 256>>>(x, Wg, G);
    k_aggr_part<<<dim3(2, 2, 96), 256>>>(Adj, G, P);
    k_red<<<PLANE_H / 256, 256>>>(P, bg, H0);
    k_gemm_nn<<<dim3(2, 64, 1), 256>>>(H0, Td, HT);
    k_ahat<<<dim3(2, 2, BGRP), 256>>>(HT, H0, Ablk);

    // layer-1 adjacency
    cudaMemsetAsync(Adj, 0, 3 * ADJ1 * sizeof(float));
    k_scatter_A<<<NEDGE / 256, 256>>>(ei_e, Ablk, Adj);
    k_scatter_A<<<NEDGE / 256, 256>>>(ei_p, Ablk, Adj + ADJ1);
    k_scatter_A<<<NEDGE / 256, 256>>>(ei_o, Ablk, Adj + 2 * ADJ1);

    // layer 1
    k_gemm_nn<<<dim3(2, 64, 3), 256>>>(H0, Wg + 3 * DDIM * DDIM, G);
    k_aggr_part<<<dim3(2, 2, 96), 256>>>(Adj, G, P);
    k_red<<<PLANE_H / 256, 256>>>(P, bg + 3 * DDIM, H1);
    k_gemm_nn<<<dim3(2, 64, 1), 256>>>(H1, Td + DDIM * DDIM, HT);
    k_ahat<<<dim3(2, 2, BGRP), 256>>>(HT, H1, Ablk);

    // final maps
    k_final<<<BGRP, 256>>>(Ablk, emf, pmf, out);
}